// round 5
// baseline (speedup 1.0000x reference)
#include <cuda_runtime.h>
#include <cstdint>

#define BB 8
#define MM 8192
#define DD 1024
#define GG 512

// Scratch (module globals; no runtime allocation)
__device__ float g_qzr[(size_t)BB * MM * DD];  // 268 MB: tf32-rounded qz
__device__ float g_qg[(size_t)BB * MM * GG];   // 134 MB: tf32-rounded relu(qz @ W^T)
__device__ float g_Wr[(size_t)BB * GG * DD];   // 16.8 MB: tf32-rounded W [b,g,d]
__device__ float g_Wt[(size_t)BB * DD * GG];   // 16.8 MB: tf32-rounded W^T [b,d,g]
__device__ float g_psum[(size_t)BB * 64 * 4 * 128];  // per-CTA partial row L1 sums

__device__ __forceinline__ float to_tf32(float x) {
    float y; asm("cvt.rna.tf32.f32 %0,%1;" : "=f"(y) : "f"(x)); return y;
}
__device__ __forceinline__ void ldsm4(uint32_t r[4], uint32_t addr) {
    asm volatile("ldmatrix.sync.aligned.m8n8.x4.shared.b16 {%0,%1,%2,%3}, [%4];"
        : "=r"(r[0]), "=r"(r[1]), "=r"(r[2]), "=r"(r[3]) : "r"(addr));
}
__device__ __forceinline__ void mma8(float c[4], const uint32_t a[4],
                                     uint32_t b0, uint32_t b1) {
    asm volatile(
        "mma.sync.aligned.m16n8k8.row.col.f32.tf32.tf32.f32 "
        "{%0,%1,%2,%3},{%4,%5,%6,%7},{%8,%9},{%0,%1,%2,%3};"
        : "+f"(c[0]), "+f"(c[1]), "+f"(c[2]), "+f"(c[3])
        : "r"(a[0]), "r"(a[1]), "r"(a[2]), "r"(a[3]), "r"(b0), "r"(b1));
}
__device__ __forceinline__ uint32_t smem_u32(const void* p) {
    uint32_t a;
    asm("{ .reg .u64 t; cvta.to.shared.u64 t, %1; cvt.u32.u64 %0, t; }" : "=r"(a) : "l"(p));
    return a;
}
#define CPA(dst, src) \
    asm volatile("cp.async.cg.shared.global [%0], [%1], 16;" :: "r"(dst), "l"(src) : "memory")
#define CPA_COMMIT() asm volatile("cp.async.commit_group;" ::: "memory")
#define CPA_WAIT(n)  asm volatile("cp.async.wait_group %0;" :: "n"(n) : "memory")

// ---------------------------------------------------------------------------
// Prep: round qz; round+transpose W (one pass -> g_Wr and g_Wt)
// ---------------------------------------------------------------------------
__global__ __launch_bounds__(256) void round_qz(const float* __restrict__ qz) {
    size_t i = ((size_t)blockIdx.x * 256 + threadIdx.x) * 4;
    float4 v = *(const float4*)(qz + i);
    v.x = to_tf32(v.x); v.y = to_tf32(v.y); v.z = to_tf32(v.z); v.w = to_tf32(v.w);
    *(float4*)(g_qzr + i) = v;
}
__global__ __launch_bounds__(256) void prep_W(const float* __restrict__ W) {
    __shared__ float t[32][33];
    int b = blockIdx.z;
    int d0 = blockIdx.x * 32, g0 = blockIdx.y * 32;
    int x = threadIdx.x & 31, y = threadIdx.x >> 5;
    const float* src = W + (size_t)b * GG * DD;
    float* dstT = g_Wt + (size_t)b * DD * GG;
    float* dstR = g_Wr + (size_t)b * GG * DD;
#pragma unroll
    for (int i = 0; i < 32; i += 8) {
        float v = to_tf32(src[(size_t)(g0 + y + i) * DD + d0 + x]);
        t[y + i][x] = v;
        dstR[(size_t)(g0 + y + i) * DD + d0 + x] = v;
    }
    __syncthreads();
#pragma unroll
    for (int i = 0; i < 32; i += 8)
        dstT[(size_t)(d0 + y + i) * GG + g0 + x] = t[x][y + i];
}

// ---------------------------------------------------------------------------
// NT GEMM: C[128x128] = A[128 x KTOT] * B[128 x KTOT]^T, K-major, all operands
// pre-rounded tf32 -> pure cp.async, 3-stage ring, ONE barrier per iteration.
// 4 warps, warp tile 64x64, XOR-swizzled smem, ldmatrix, frag double-buffer.
// EPI 0: relu + tf32 round -> g_qg; per-CTA row partial L1 sums -> g_psum.
// EPI 1: inv = 1/max(sum of 4 partials, eps) in prologue; rows scaled -> out.
// ---------------------------------------------------------------------------
template<int KTOT, int EPI>
__global__ __launch_bounds__(128) void gemm_v5(float* __restrict__ Cout)
{
    constexpr int BK = 32;
    constexpr int NK = KTOT / BK;
    constexpr int LDC = (EPI == 0) ? GG : DD;
    // smem: A stages @ s*16384 (3), B stages @ 49152 + s*16384 (3), sinv @ 98304
    extern __shared__ __align__(128) char smem[];
    const uint32_t sb = smem_u32(smem);

    const int t    = threadIdx.x;
    const int lane = t & 31, w = t >> 5;
    const int gid  = lane >> 2, tig = lane & 3;
    const int warp_m = (w & 1) * 64;
    const int warp_n = (w >> 1) * 64;
    const int bx = blockIdx.x, by = blockIdx.y, b = blockIdx.z;
    const int bm = bx * 128, bn = by * 128;

    const float* Ag = ((EPI == 0) ? g_qzr : g_qg) + ((size_t)b * MM + bm) * KTOT;
    const float* Bg = ((EPI == 0) ? g_Wr : g_Wt) + ((size_t)b * LDC + bn) * KTOT;
    float* Cg = ((EPI == 0) ? g_qg : Cout) + ((size_t)b * MM + bm) * LDC + bn;

    // EPI1: build per-row inverse L1 norms from the 4 partials
    float* sinv = (float*)(smem + 98304);
    if (EPI == 1 && t < 128) {
        const float* ps = &g_psum[((size_t)(b * 64 + bx) * 4) * 128];
        float s = ps[t] + ps[128 + t] + ps[256 + t] + ps[384 + t];
        sinv[t] = 1.f / fmaxf(s, 1e-6f);
    }

    float acc[4][8][4];
#pragma unroll
    for (int i = 0; i < 4; i++)
#pragma unroll
        for (int j = 0; j < 8; j++)
#pragma unroll
            for (int k = 0; k < 4; k++) acc[i][j][k] = 0.f;

    // one stage = A 128x32 + B 128x32, 16B chunks, XOR-swizzled
    auto ISSUE = [&](int it) {
        const int k0 = it * BK;
        const int s = it % 3;
        const uint32_t abase = sb + s * 16384;
        const uint32_t bbase = sb + 49152 + s * 16384;
#pragma unroll
        for (int j = 0; j < 8; j++) {
            int i = t + j * 128, row = i >> 3, g = i & 7;
            uint32_t off = (uint32_t)(row * 128) + (uint32_t)((g ^ (row & 7)) << 4);
            CPA(abase + off, Ag + (size_t)row * KTOT + k0 + g * 4);
            CPA(bbase + off, Bg + (size_t)row * KTOT + k0 + g * 4);
        }
    };

    // ldmatrix lane-address components
    const int mat   = lane >> 3;
    const int rsub  = (mat & 1) * 8 + (lane & 7);
    const int ghalf = mat >> 1;

    uint32_t fA[2][4][4], fB[2][4][4];
    auto LDFRAG = [&](int s, int ks, int pb) {
        const uint32_t abase = sb + s * 16384;
        const uint32_t bbase = sb + 49152 + s * 16384;
        const int grp = 2 * ks + ghalf;
#pragma unroll
        for (int mf = 0; mf < 4; mf++) {
            int rr = warp_m + mf * 16 + rsub;
            ldsm4(fA[pb][mf], abase + rr * 128 + ((grp ^ (rr & 7)) << 4));
        }
#pragma unroll
        for (int nb = 0; nb < 4; nb++) {
            int rr = warp_n + nb * 16 + rsub;
            ldsm4(fB[pb][nb], bbase + rr * 128 + ((grp ^ (rr & 7)) << 4));
        }
    };
    auto MMAS = [&](int pb) {
#pragma unroll
        for (int nb = 0; nb < 4; nb++)
#pragma unroll
            for (int mf = 0; mf < 4; mf++) {
                mma8(acc[mf][2 * nb],     fA[pb][mf], fB[pb][nb][0], fB[pb][nb][2]);
                mma8(acc[mf][2 * nb + 1], fA[pb][mf], fB[pb][nb][1], fB[pb][nb][3]);
            }
    };

    // prologue: 2 stages in flight
    ISSUE(0); CPA_COMMIT();
    ISSUE(1); CPA_COMMIT();

#pragma unroll 1
    for (int it = 0; it < NK; ++it) {
        if (it + 1 < NK) CPA_WAIT(1); else CPA_WAIT(0);
        __syncthreads();                       // stage `it` visible; COMP(it-1) done by all
        if (it + 2 < NK) { ISSUE(it + 2); CPA_COMMIT(); }
        const int s = it % 3;
        LDFRAG(s, 0, 0);
#pragma unroll
        for (int ks = 0; ks < 4; ks++) {
            if (ks < 3) LDFRAG(s, ks + 1, (ks + 1) & 1);
            MMAS(ks & 1);
        }
    }

    // ---- epilogue ----
    float s0[4], s1[4];
#pragma unroll
    for (int mf = 0; mf < 4; mf++) { s0[mf] = 0.f; s1[mf] = 0.f; }

#pragma unroll
    for (int mf = 0; mf < 4; mf++) {
        int r0 = warp_m + mf * 16 + gid;
        float i0 = 1.f, i1 = 1.f;
        if (EPI == 1) { i0 = sinv[r0]; i1 = sinv[r0 + 8]; }
#pragma unroll
        for (int nf = 0; nf < 8; nf++) {
            int c0 = warp_n + nf * 8 + tig * 2;
            float2 v0, v1;
            if (EPI == 0) {
                v0 = make_float2(to_tf32(fmaxf(acc[mf][nf][0], 0.f)),
                                 to_tf32(fmaxf(acc[mf][nf][1], 0.f)));
                v1 = make_float2(to_tf32(fmaxf(acc[mf][nf][2], 0.f)),
                                 to_tf32(fmaxf(acc[mf][nf][3], 0.f)));
                s0[mf] += v0.x + v0.y;
                s1[mf] += v1.x + v1.y;
            } else {
                v0 = make_float2(acc[mf][nf][0] * i0, acc[mf][nf][1] * i0);
                v1 = make_float2(acc[mf][nf][2] * i1, acc[mf][nf][3] * i1);
            }
            *(float2*)(Cg + (size_t)r0 * LDC + c0)       = v0;
            *(float2*)(Cg + (size_t)(r0 + 8) * LDC + c0) = v1;
        }
    }

    if (EPI == 0) {
        // reduce partial sums across the 4 lanes sharing each row
#pragma unroll
        for (int mf = 0; mf < 4; mf++) {
            s0[mf] += __shfl_xor_sync(0xffffffffu, s0[mf], 1);
            s0[mf] += __shfl_xor_sync(0xffffffffu, s0[mf], 2);
            s1[mf] += __shfl_xor_sync(0xffffffffu, s1[mf], 1);
            s1[mf] += __shfl_xor_sync(0xffffffffu, s1[mf], 2);
        }
        __syncthreads();                        // stages no longer needed; reuse smem
        float* ps = (float*)smem;               // [2][128]: per n-half row sums
        if (tig == 0) {
#pragma unroll
            for (int mf = 0; mf < 4; mf++) {
                int r0 = warp_m + mf * 16 + gid;
                ps[(w >> 1) * 128 + r0]     = s0[mf];
                ps[(w >> 1) * 128 + r0 + 8] = s1[mf];
            }
        }
        __syncthreads();
        if (t < 128)
            g_psum[((size_t)(b * 64 + bx) * 4 + by) * 128 + t] = ps[t] + ps[128 + t];
    }
}

// ---------------------------------------------------------------------------
extern "C" void kernel_launch(void* const* d_in, const int* in_sizes, int n_in,
                              void* d_out, int out_size)
{
    const float* qz = (const float*)d_in[0];
    const float* W  = (const float*)d_in[1];
    float* out = (float*)d_out;

    constexpr int SMEM = 98816;  // 3x16KB A + 3x16KB B + 512B sinv
    cudaFuncSetAttribute(gemm_v5<1024, 0>, cudaFuncAttributeMaxDynamicSharedMemorySize, SMEM);
    cudaFuncSetAttribute(gemm_v5<512, 1>,  cudaFuncAttributeMaxDynamicSharedMemorySize, SMEM);

    round_qz<<<(size_t)BB * MM * DD / (256 * 4), 256>>>(qz);
    prep_W<<<dim3(DD / 32, GG / 32, BB), 256>>>(W);

    // qg = tf32(relu(qz @ W^T)) + per-CTA row partials  [K = 1024]
    gemm_v5<1024, 0><<<dim3(MM / 128, GG / 128, BB), 128, SMEM>>>(nullptr);

    // msg = (qg / L1) @ W  via Wt  [K = 512], norm built from partials
    gemm_v5<512, 1><<<dim3(MM / 128, DD / 128, BB), 128, SMEM>>>(out);
}